// round 13
// baseline (speedup 1.0000x reference)
#include <cuda_runtime.h>
#include <cuda_bf16.h>
#include <cuda_fp16.h>
#include <math.h>
#include <stdint.h>

#define N_NODES 50000
#define N_EDGES 800000
#define NH 4
#define FOUT 32
#define FIN 128          // = NH*FOUT
#define LEAKY 0.2f
#define NB_CHUNKS ((N_NODES + 255) / 256)   // 196

// ---------------- device scratch (static, allocation-free) ----------------
__device__ __align__(16) __half g_projh[N_NODES * FIN];     // 12.8 MB (fp16 proj)
__device__ __align__(16) float g_s_src[N_NODES * NH];
__device__ __align__(16) float g_s_trg[N_NODES * NH];
__device__ float g_max;
__device__ int g_total;
__device__ int g_cnt[N_NODES];
__device__ int g_off[N_NODES];
__device__ int g_cur[N_NODES];
__device__ int g_esrc[N_EDGES];
// bf16 hi/lo images of B = W^T, laid out [n][k] row-major (unpadded)
__device__ __align__(16) unsigned short g_Bhi[FIN * FIN];
__device__ __align__(16) unsigned short g_Blo[FIN * FIN];

// ---------------- helpers ----------------
__device__ __forceinline__ void atomicMaxFloat(float* addr, float value) {
    if (value >= 0.f) atomicMax((int*)addr, __float_as_int(value));
    else              atomicMin((unsigned int*)addr, __float_as_uint(value));
}

__device__ __forceinline__ uint32_t smem_u32(const void* p) {
    uint32_t a;
    asm("{ .reg .u64 t; cvta.to.shared.u64 t, %1; cvt.u32.u64 %0, t; }" : "=r"(a) : "l"(p));
    return a;
}

__device__ __forceinline__ void mma16816(float c[4], const uint32_t a[4], const uint32_t b[2]) {
    asm volatile(
        "mma.sync.aligned.m16n8k16.row.col.f32.bf16.bf16.f32 "
        "{%0,%1,%2,%3}, {%4,%5,%6,%7}, {%8,%9}, {%0,%1,%2,%3};"
        : "+f"(c[0]), "+f"(c[1]), "+f"(c[2]), "+f"(c[3])
        : "r"(a[0]), "r"(a[1]), "r"(a[2]), "r"(a[3]), "r"(b[0]), "r"(b[1]));
}

#define LDSM4(r0, r1, r2, r3, addr) \
    asm volatile("ldmatrix.sync.aligned.m8n8.x4.shared.b16 {%0,%1,%2,%3}, [%4];" \
                 : "=r"(r0), "=r"(r1), "=r"(r2), "=r"(r3) : "r"(addr))

__device__ __forceinline__ float leaky(float v) { return v > 0.f ? v : LEAKY * v; }

// ---------------- MAIN branch head: W conversion + g_max reset -----------
__global__ void k_wconv(const float* __restrict__ W) {
    int i = blockIdx.x * blockDim.x + threadIdx.x;
    if (i == 0) g_max = __uint_as_float(0xFF800000u);
    if (i < FIN * FIN) {
        int k = i >> 7, n = i & 127;
        float v = W[i];                       // W[k][n]
        __nv_bfloat16 hi = __float2bfloat16(v);
        __nv_bfloat16 lo = __float2bfloat16(v - __bfloat162float(hi));
        g_Bhi[n * FIN + k] = __bfloat16_as_ushort(hi);
        g_Blo[n * FIN + k] = __bfloat16_as_ushort(lo);
    }
}

// ---------------- S2 branch head: zero counts + total --------------------
__global__ void k_zero() {
    int i = blockIdx.x * blockDim.x + threadIdx.x;
    if (i < N_NODES) g_cnt[i] = 0;
    if (i == 0) g_total = 0;
}

// ---------------- kernel: count in-degree (x4 MLP) -----------------------
__global__ void k_count(const int* __restrict__ ei, int E) {
    int base = (blockIdx.x * blockDim.x + threadIdx.x) * 4;
    if (base + 3 < E) {
        int4 t = *(const int4*)&ei[E + base];
        atomicAdd(&g_cnt[t.x], 1);
        atomicAdd(&g_cnt[t.y], 1);
        atomicAdd(&g_cnt[t.z], 1);
        atomicAdd(&g_cnt[t.w], 1);
    } else {
        for (int i = base; i < E; i++) atomicAdd(&g_cnt[ei[E + i]], 1);
    }
}

// ---------------- kernel: CSR offsets ------------------------------------
__global__ void k_offsets() {
    __shared__ int s[256];
    __shared__ int sbase;
    int t = threadIdx.x, i = blockIdx.x * 256 + t;
    int v = (i < N_NODES) ? g_cnt[i] : 0;
    s[t] = v;
    __syncthreads();
#pragma unroll
    for (int o = 1; o < 256; o <<= 1) {
        int u = (t >= o) ? s[t - o] : 0;
        __syncthreads();
        s[t] += u;
        __syncthreads();
    }
    if (t == 255) sbase = atomicAdd(&g_total, s[255]);
    __syncthreads();
    if (i < N_NODES) {
        int off = sbase + s[t] - v;
        g_off[i] = off;
        g_cur[i] = off;
    }
}

// ---------------- kernel: scatter edges into CSR (x4 MLP) ----------------
__global__ void k_scatter(const int* __restrict__ ei, int E) {
    int base = (blockIdx.x * blockDim.x + threadIdx.x) * 4;
    if (base + 3 < E) {
        int4 s = *(const int4*)&ei[base];
        int4 t = *(const int4*)&ei[E + base];
        int p0 = atomicAdd(&g_cur[t.x], 1);
        int p1 = atomicAdd(&g_cur[t.y], 1);
        int p2 = atomicAdd(&g_cur[t.z], 1);
        int p3 = atomicAdd(&g_cur[t.w], 1);
        g_esrc[p0] = s.x;
        g_esrc[p1] = s.y;
        g_esrc[p2] = s.z;
        g_esrc[p3] = s.w;
    } else {
        for (int i = base; i < E; i++) {
            int pos = atomicAdd(&g_cur[ei[E + i]], 1);
            g_esrc[pos] = ei[i];
        }
    }
}

// ---------------- HMMA GEMM: proj = x@W (split bf16), + s_src/s_trg ------
// CTA = 64 rows x 64 cols. smem 69.6 KB -> 3 CTAs/SM. 8 warps, warp tile 32x16.
#define CROWS 64
#define CCOLS 64
#define PADK 136
#define OFF_A_HI 0
#define OFF_A_LO (CROWS * PADK * 2)             // 17408
#define OFF_B_HI (OFF_A_LO + CROWS * PADK * 2)  // 34816
#define OFF_B_LO (OFF_B_HI + CCOLS * PADK * 2)  // 52224
#define GEMM_SMEM (OFF_B_LO + CCOLS * PADK * 2) // 69632
#define BSTRIDE 68                               // bounce stride (floats)

__global__ __launch_bounds__(256, 3) void k_gemm_mma(const float* __restrict__ x,
                                                     const float* __restrict__ a_src,
                                                     const float* __restrict__ a_trg) {
    extern __shared__ char smem[];
    unsigned short* A_hi = (unsigned short*)(smem + OFF_A_HI);
    unsigned short* A_lo = (unsigned short*)(smem + OFF_A_LO);
    unsigned short* B_hi = (unsigned short*)(smem + OFF_B_HI);
    unsigned short* B_lo = (unsigned short*)(smem + OFF_B_LO);

    const int tid = threadIdx.x;
    const int wid = tid >> 5, lane = tid & 31;
    const int row0 = blockIdx.x * CROWS;
    const int col0 = blockIdx.y * CCOLS;

    // ---- load x tile (64 rows, full K), split to bf16 hi/lo ----
    for (int idx = tid; idx < CROWS * 16; idx += 256) {   // 4 iters
        int r = idx >> 4, c8 = idx & 15;
        int gr = row0 + r;
        float v[8];
        if (gr < N_NODES) {
            float4 p0 = *(const float4*)&x[(size_t)gr * FIN + c8 * 8];
            float4 p1 = *(const float4*)&x[(size_t)gr * FIN + c8 * 8 + 4];
            v[0]=p0.x; v[1]=p0.y; v[2]=p0.z; v[3]=p0.w;
            v[4]=p1.x; v[5]=p1.y; v[6]=p1.z; v[7]=p1.w;
        } else {
#pragma unroll
            for (int j = 0; j < 8; j++) v[j] = 0.f;
        }
        uint32_t hp[4], lp[4];
#pragma unroll
        for (int j = 0; j < 4; j++) {
            __nv_bfloat16 h0 = __float2bfloat16(v[2*j]);
            __nv_bfloat16 h1 = __float2bfloat16(v[2*j+1]);
            __nv_bfloat16 l0 = __float2bfloat16(v[2*j]   - __bfloat162float(h0));
            __nv_bfloat16 l1 = __float2bfloat16(v[2*j+1] - __bfloat162float(h1));
            hp[j] = (uint32_t)__bfloat16_as_ushort(h0) | ((uint32_t)__bfloat16_as_ushort(h1) << 16);
            lp[j] = (uint32_t)__bfloat16_as_ushort(l0) | ((uint32_t)__bfloat16_as_ushort(l1) << 16);
        }
        *(uint4*)&A_hi[r * PADK + c8 * 8] = make_uint4(hp[0], hp[1], hp[2], hp[3]);
        *(uint4*)&A_lo[r * PADK + c8 * 8] = make_uint4(lp[0], lp[1], lp[2], lp[3]);
    }
    // ---- copy this CTA's 64-col half of B images ----
    for (int idx = tid; idx < 1024; idx += 256) {
        int n = idx >> 4, q = idx & 15;
        *(uint4*)&B_hi[n * PADK + q * 8] = *(const uint4*)&g_Bhi[(col0 + n) * FIN + q * 8];
        *(uint4*)&B_lo[n * PADK + q * 8] = *(const uint4*)&g_Blo[(col0 + n) * FIN + q * 8];
    }
    __syncthreads();

    // ---- mainloop: ldmatrix fragments, 3 passes ----
    const int m0 = (wid & 1) * 32;
    const int n0 = (wid >> 1) * 16;
    const int lr = lane >> 2;
    const int lc = (lane & 3) * 2;

    const uint32_t sbu = smem_u32(smem);
    const int a_row = m0 + (lane & 15);
    const int a_c8  = (lane >> 4) * 8;
    const uint32_t aH0 = sbu + OFF_A_HI + (uint32_t)(a_row * PADK + a_c8) * 2;
    const uint32_t aL0 = sbu + OFF_A_LO + (uint32_t)(a_row * PADK + a_c8) * 2;
    const int b_row = n0 + ((lane >> 4) << 3) + (lane & 7);
    const int b_c8  = ((lane >> 3) & 1) * 8;
    const uint32_t bH0 = sbu + OFF_B_HI + (uint32_t)(b_row * PADK + b_c8) * 2;
    const uint32_t bL0 = sbu + OFF_B_LO + (uint32_t)(b_row * PADK + b_c8) * 2;
    const uint32_t STEP16 = 16 * PADK * 2;

    float c[2][2][4];
#pragma unroll
    for (int mi = 0; mi < 2; mi++)
#pragma unroll
        for (int ni = 0; ni < 2; ni++)
#pragma unroll
            for (int r = 0; r < 4; r++) c[mi][ni][r] = 0.f;

#pragma unroll
    for (int ks = 0; ks < 8; ks++) {
        const uint32_t koff = (uint32_t)(ks * 32);
        uint32_t ah[2][4], al[2][4], bh[2][2], bl[2][2];
        LDSM4(ah[0][0], ah[0][1], ah[0][2], ah[0][3], aH0 + koff);
        LDSM4(ah[1][0], ah[1][1], ah[1][2], ah[1][3], aH0 + STEP16 + koff);
        LDSM4(al[0][0], al[0][1], al[0][2], al[0][3], aL0 + koff);
        LDSM4(al[1][0], al[1][1], al[1][2], al[1][3], aL0 + STEP16 + koff);
        LDSM4(bh[0][0], bh[0][1], bh[1][0], bh[1][1], bH0 + koff);
        LDSM4(bl[0][0], bl[0][1], bl[1][0], bl[1][1], bL0 + koff);
#pragma unroll
        for (int mi = 0; mi < 2; mi++)
#pragma unroll
            for (int ni = 0; ni < 2; ni++) {
                mma16816(c[mi][ni], ah[mi], bh[ni]);
                mma16816(c[mi][ni], ah[mi], bl[ni]);
                mma16816(c[mi][ni], al[mi], bh[ni]);
            }
    }
    __syncthreads();

    // ---- bounce accumulators to smem ----
    float* bounce = (float*)smem;             // [64][68]
#pragma unroll
    for (int mi = 0; mi < 2; mi++) {
        int row = m0 + mi * 16 + lr;
#pragma unroll
        for (int ni = 0; ni < 2; ni++) {
            int col = n0 + ni * 8 + lc;
            bounce[row * BSTRIDE + col]           = c[mi][ni][0];
            bounce[row * BSTRIDE + col + 1]       = c[mi][ni][1];
            bounce[(row + 8) * BSTRIDE + col]     = c[mi][ni][2];
            bounce[(row + 8) * BSTRIDE + col + 1] = c[mi][ni][3];
        }
    }
    __syncthreads();

    // ---- per-row head dots ----
    if (tid < 128) {
        int r = tid >> 1, hl = tid & 1;
        int gr = row0 + r;
        if (gr < N_NODES) {
            int h = (col0 >> 5) + hl;
            const float* rowp = &bounce[r * BSTRIDE + hl * 32];
            float ps = 0.f, pt = 0.f;
#pragma unroll
            for (int j = 0; j < 32; j++) {
                float vv = rowp[j];
                ps = fmaf(vv, __ldg(&a_src[h * 32 + j]), ps);
                pt = fmaf(vv, __ldg(&a_trg[h * 32 + j]), pt);
            }
            g_s_src[gr * NH + h] = ps;
            g_s_trg[gr * NH + h] = pt;
        }
    }

    // ---- coalesced fp16 proj copy-out ----
    const int valid = min(CROWS, N_NODES - row0);
    for (int idx = tid; idx < valid * 32; idx += 256) {
        int r = idx >> 5, c2i = idx & 31;
        float2 f = make_float2(bounce[r * BSTRIDE + c2i * 2],
                               bounce[r * BSTRIDE + c2i * 2 + 1]);
        ((__half2*)&g_projh[(size_t)(row0 + r) * FIN + col0])[c2i] = __float22half2_rn(f);
    }
}

// ---------------- kernel: global max over leaky edge scores (x4 MLP) -----
__global__ void k_edge_max(const int* __restrict__ ei, int E) {
    float m = __uint_as_float(0xFF800000u);
    int base = (blockIdx.x * blockDim.x + threadIdx.x) * 4;
    if (base + 3 < E) {
        int4 s = *(const int4*)&ei[base];
        int4 t = *(const int4*)&ei[E + base];
        float4 ss0 = *(const float4*)&g_s_src[s.x * NH];
        float4 ss1 = *(const float4*)&g_s_src[s.y * NH];
        float4 ss2 = *(const float4*)&g_s_src[s.z * NH];
        float4 ss3 = *(const float4*)&g_s_src[s.w * NH];
        float4 st0 = *(const float4*)&g_s_trg[t.x * NH];
        float4 st1 = *(const float4*)&g_s_trg[t.y * NH];
        float4 st2 = *(const float4*)&g_s_trg[t.z * NH];
        float4 st3 = *(const float4*)&g_s_trg[t.w * NH];
        float m0 = fmaxf(fmaxf(leaky(ss0.x + st0.x), leaky(ss0.y + st0.y)),
                         fmaxf(leaky(ss0.z + st0.z), leaky(ss0.w + st0.w)));
        float m1 = fmaxf(fmaxf(leaky(ss1.x + st1.x), leaky(ss1.y + st1.y)),
                         fmaxf(leaky(ss1.z + st1.z), leaky(ss1.w + st1.w)));
        float m2 = fmaxf(fmaxf(leaky(ss2.x + st2.x), leaky(ss2.y + st2.y)),
                         fmaxf(leaky(ss2.z + st2.z), leaky(ss2.w + st2.w)));
        float m3 = fmaxf(fmaxf(leaky(ss3.x + st3.x), leaky(ss3.y + st3.y)),
                         fmaxf(leaky(ss3.z + st3.z), leaky(ss3.w + st3.w)));
        m = fmaxf(fmaxf(m0, m1), fmaxf(m2, m3));
    } else {
        for (int i = base; i < E; i++) {
            float4 ss = *(const float4*)&g_s_src[ei[i] * NH];
            float4 st = *(const float4*)&g_s_trg[ei[E + i] * NH];
            m = fmaxf(m, fmaxf(fmaxf(leaky(ss.x + st.x), leaky(ss.y + st.y)),
                               fmaxf(leaky(ss.z + st.z), leaky(ss.w + st.w))));
        }
    }
#pragma unroll
    for (int o = 16; o >= 1; o >>= 1) m = fmaxf(m, __shfl_xor_sync(0xffffffffu, m, o));
    __shared__ float sm[8];
    int lane = threadIdx.x & 31, warp = threadIdx.x >> 5;
    if (lane == 0) sm[warp] = m;
    __syncthreads();
    if (warp == 0) {
        m = (lane < 8) ? sm[lane] : __uint_as_float(0xFF800000u);
#pragma unroll
        for (int o = 4; o >= 1; o >>= 1) m = fmaxf(m, __shfl_xor_sync(0xffffffffu, m, o));
        if (lane == 0) atomicMaxFloat(&g_max, m);
    }
}

// ---------------- kernel: SINGLE-PASS aggregate + skip + bias + ELU ------
__global__ __launch_bounds__(256) void k_node(const float* __restrict__ x,
                                              const float* __restrict__ bias,
                                              float* __restrict__ out) {
    int n = (blockIdx.x * blockDim.x + threadIdx.x) >> 5;
    if (n >= N_NODES) return;
    const int lane = threadIdx.x & 31;
    const int head = lane >> 3;
    const int start = g_off[n];
    const int deg = g_cnt[n];
    const float gm = g_max;
    const float st_h = g_s_trg[n * NH + head];

    float4 acc = make_float4(0.f, 0.f, 0.f, 0.f);
    float d = 0.f;

    int k = 0;
    for (; k + 3 < deg; k += 4) {
        int s0 = g_esrc[start + k];
        int s1 = g_esrc[start + k + 1];
        int s2 = g_esrc[start + k + 2];
        int s3 = g_esrc[start + k + 3];
        float sa = g_s_src[s0 * NH + head];
        float sb = g_s_src[s1 * NH + head];
        float sc = g_s_src[s2 * NH + head];
        float sd = g_s_src[s3 * NH + head];
        uint2 ha = *(const uint2*)&g_projh[(size_t)s0 * FIN + lane * 4];
        uint2 hb = *(const uint2*)&g_projh[(size_t)s1 * FIN + lane * 4];
        uint2 hc = *(const uint2*)&g_projh[(size_t)s2 * FIN + lane * 4];
        uint2 hd = *(const uint2*)&g_projh[(size_t)s3 * FIN + lane * 4];
        float ea = expf(leaky(sa + st_h) - gm);
        float eb = expf(leaky(sb + st_h) - gm);
        float ec = expf(leaky(sc + st_h) - gm);
        float ed = expf(leaky(sd + st_h) - gm);
        d += ea + eb + ec + ed;
        float2 pa0 = __half22float2(*(const __half2*)&ha.x);
        float2 pa1 = __half22float2(*(const __half2*)&ha.y);
        float2 pb0 = __half22float2(*(const __half2*)&hb.x);
        float2 pb1 = __half22float2(*(const __half2*)&hb.y);
        float2 pc0 = __half22float2(*(const __half2*)&hc.x);
        float2 pc1 = __half22float2(*(const __half2*)&hc.y);
        float2 pd0 = __half22float2(*(const __half2*)&hd.x);
        float2 pd1 = __half22float2(*(const __half2*)&hd.y);
        acc.x = fmaf(pa0.x, ea, acc.x); acc.x = fmaf(pb0.x, eb, acc.x);
        acc.x = fmaf(pc0.x, ec, acc.x); acc.x = fmaf(pd0.x, ed, acc.x);
        acc.y = fmaf(pa0.y, ea, acc.y); acc.y = fmaf(pb0.y, eb, acc.y);
        acc.y = fmaf(pc0.y, ec, acc.y); acc.y = fmaf(pd0.y, ed, acc.y);
        acc.z = fmaf(pa1.x, ea, acc.z); acc.z = fmaf(pb1.x, eb, acc.z);
        acc.z = fmaf(pc1.x, ec, acc.z); acc.z = fmaf(pd1.x, ed, acc.z);
        acc.w = fmaf(pa1.y, ea, acc.w); acc.w = fmaf(pb1.y, eb, acc.w);
        acc.w = fmaf(pc1.y, ec, acc.w); acc.w = fmaf(pd1.y, ed, acc.w);
    }
    for (; k < deg; k++) {
        int s0 = g_esrc[start + k];
        float sa = g_s_src[s0 * NH + head];
        uint2 ha = *(const uint2*)&g_projh[(size_t)s0 * FIN + lane * 4];
        float ea = expf(leaky(sa + st_h) - gm);
        d += ea;
        float2 pa0 = __half22float2(*(const __half2*)&ha.x);
        float2 pa1 = __half22float2(*(const __half2*)&ha.y);
        acc.x = fmaf(pa0.x, ea, acc.x);
        acc.y = fmaf(pa0.y, ea, acc.y);
        acc.z = fmaf(pa1.x, ea, acc.z);
        acc.w = fmaf(pa1.y, ea, acc.w);
    }

    const float rd = 1.f / (d + 1e-16f);
    float4 xb = *(const float4*)&x[n * FIN + lane * 4];
    float4 bb = *(const float4*)&bias[lane * 4];
    float4 r;
    r.x = fmaf(acc.x, rd, xb.x + bb.x); r.x = r.x > 0.f ? r.x : expm1f(r.x);
    r.y = fmaf(acc.y, rd, xb.y + bb.y); r.y = r.y > 0.f ? r.y : expm1f(r.y);
    r.z = fmaf(acc.z, rd, xb.z + bb.z); r.z = r.z > 0.f ? r.z : expm1f(r.z);
    r.w = fmaf(acc.w, rd, xb.w + bb.w); r.w = r.w > 0.f ? r.w : expm1f(r.w);
    *(float4*)&out[n * FIN + lane * 4] = r;
}

// ---------------- launch: two branches from capture start ----------------
extern "C" void kernel_launch(void* const* d_in, const int* in_sizes, int n_in,
                              void* d_out, int out_size) {
    const float* x     = (const float*)d_in[0];
    const int*   ei    = (const int*)d_in[1];   // JAX x64 disabled: int32
    const float* W     = (const float*)d_in[2];
    const float* a_src = (const float*)d_in[3];
    const float* a_trg = (const float*)d_in[4];
    const float* bias  = (const float*)d_in[5];
    float* out = (float*)d_out;

    const int E = in_sizes[1] / 2;
    const int EB4 = (E / 4 + 255) / 256;        // blocks for x4-unrolled edge kernels

    static cudaStream_t s2 = nullptr;
    static cudaEvent_t evFork = nullptr, evJoin = nullptr;
    if (s2 == nullptr) {
        cudaStreamCreateWithFlags(&s2, cudaStreamNonBlocking);
        cudaEventCreateWithFlags(&evFork, cudaEventDisableTiming);
        cudaEventCreateWithFlags(&evJoin, cudaEventDisableTiming);
        cudaFuncSetAttribute(k_gemm_mma, cudaFuncAttributeMaxDynamicSharedMemorySize, GEMM_SMEM);
    }

    // fork immediately: s2 = CSR branch, main = GEMM branch
    cudaEventRecord(evFork, 0);
    cudaStreamWaitEvent(s2, evFork, 0);

    // s2 branch: zero -> count -> offsets -> scatter
    k_zero<<<NB_CHUNKS, 256, 0, s2>>>();
    k_count<<<EB4, 256, 0, s2>>>(ei, E);
    k_offsets<<<NB_CHUNKS, 256, 0, s2>>>();
    k_scatter<<<EB4, 256, 0, s2>>>(ei, E);
    cudaEventRecord(evJoin, s2);

    // main branch: wconv -> GEMM -> edge max
    k_wconv<<<(FIN * FIN + 255) / 256, 256>>>(W);
    dim3 ggrid((N_NODES + CROWS - 1) / CROWS, FIN / CCOLS);
    k_gemm_mma<<<ggrid, 256, GEMM_SMEM>>>(x, a_src, a_trg);
    k_edge_max<<<EB4, 256>>>(ei, E);

    // join: node needs CSR + scores + max
    cudaStreamWaitEvent(0, evJoin, 0);
    k_node<<<(N_NODES * 32 + 255) / 256, 256>>>(x, bias, out);
}

// round 14
// speedup vs baseline: 1.1861x; 1.1861x over previous
#include <cuda_runtime.h>
#include <cuda_bf16.h>
#include <cuda_fp16.h>
#include <math.h>
#include <stdint.h>

#define N_NODES 50000
#define N_EDGES 800000
#define NH 4
#define FOUT 32
#define FIN 128          // = NH*FOUT
#define LEAKY 0.2f
#define NB_CHUNKS ((N_NODES + 255) / 256)   // 196

// ---------------- device scratch (static, allocation-free) ----------------
__device__ __align__(16) __half g_projh[N_NODES * FIN];     // 12.8 MB (fp16 proj)
__device__ __align__(16) float g_s_src[N_NODES * NH];
__device__ __align__(16) float g_s_trg[N_NODES * NH];
__device__ float g_max;
__device__ int g_total;
__device__ int g_cnt[N_NODES];
__device__ int g_off[N_NODES];
__device__ int g_cur[N_NODES];
__device__ int g_esrc[N_EDGES];
// bf16 hi/lo images of B = W^T, laid out [n][k] row-major (unpadded)
__device__ __align__(16) unsigned short g_Bhi[FIN * FIN];
__device__ __align__(16) unsigned short g_Blo[FIN * FIN];

// ---------------- helpers ----------------
__device__ __forceinline__ void atomicMaxFloat(float* addr, float value) {
    if (value >= 0.f) atomicMax((int*)addr, __float_as_int(value));
    else              atomicMin((unsigned int*)addr, __float_as_uint(value));
}

__device__ __forceinline__ uint32_t smem_u32(const void* p) {
    uint32_t a;
    asm("{ .reg .u64 t; cvta.to.shared.u64 t, %1; cvt.u32.u64 %0, t; }" : "=r"(a) : "l"(p));
    return a;
}

__device__ __forceinline__ void mma16816(float c[4], const uint32_t a[4], const uint32_t b[2]) {
    asm volatile(
        "mma.sync.aligned.m16n8k16.row.col.f32.bf16.bf16.f32 "
        "{%0,%1,%2,%3}, {%4,%5,%6,%7}, {%8,%9}, {%0,%1,%2,%3};"
        : "+f"(c[0]), "+f"(c[1]), "+f"(c[2]), "+f"(c[3])
        : "r"(a[0]), "r"(a[1]), "r"(a[2]), "r"(a[3]), "r"(b[0]), "r"(b[1]));
}

#define LDSM4(r0, r1, r2, r3, addr) \
    asm volatile("ldmatrix.sync.aligned.m8n8.x4.shared.b16 {%0,%1,%2,%3}, [%4];" \
                 : "=r"(r0), "=r"(r1), "=r"(r2), "=r"(r3) : "r"(addr))

__device__ __forceinline__ float leaky(float v) { return v > 0.f ? v : LEAKY * v; }

// ---------------- kernel: zero counts + reset max + W conversion ---------
__global__ void k_init(const float* __restrict__ W) {
    int i = blockIdx.x * blockDim.x + threadIdx.x;
    if (i < N_NODES) g_cnt[i] = 0;
    if (i == 0) { g_max = __uint_as_float(0xFF800000u); g_total = 0; }
    if (i < FIN * FIN) {
        int k = i >> 7, n = i & 127;
        float v = W[i];                       // W[k][n]
        __nv_bfloat16 hi = __float2bfloat16(v);
        __nv_bfloat16 lo = __float2bfloat16(v - __bfloat162float(hi));
        g_Bhi[n * FIN + k] = __bfloat16_as_ushort(hi);
        g_Blo[n * FIN + k] = __bfloat16_as_ushort(lo);
    }
}

// ---------------- kernel: count in-degree --------------------------------
__global__ void k_count(const int* __restrict__ ei, int E) {
    int i = blockIdx.x * blockDim.x + threadIdx.x;
    if (i < E) atomicAdd(&g_cnt[ei[E + i]], 1);
}

// ---------------- kernel: CSR offsets ------------------------------------
__global__ void k_offsets() {
    __shared__ int s[256];
    __shared__ int sbase;
    int t = threadIdx.x, i = blockIdx.x * 256 + t;
    int v = (i < N_NODES) ? g_cnt[i] : 0;
    s[t] = v;
    __syncthreads();
#pragma unroll
    for (int o = 1; o < 256; o <<= 1) {
        int u = (t >= o) ? s[t - o] : 0;
        __syncthreads();
        s[t] += u;
        __syncthreads();
    }
    if (t == 255) sbase = atomicAdd(&g_total, s[255]);
    __syncthreads();
    if (i < N_NODES) {
        int off = sbase + s[t] - v;
        g_off[i] = off;
        g_cur[i] = off;
    }
}

// ---------------- kernel: scatter edges into CSR --------------------------
__global__ void k_scatter(const int* __restrict__ ei, int E) {
    int i = blockIdx.x * blockDim.x + threadIdx.x;
    if (i >= E) return;
    int src = ei[i];
    int trg = ei[E + i];
    int pos = atomicAdd(&g_cur[trg], 1);
    g_esrc[pos] = src;
}

// ---------------- HMMA GEMM: proj = x@W (split bf16), + s_src/s_trg ------
// CTA = 64 rows x 64 cols. smem 69.6 KB -> 3 CTAs/SM. 8 warps, warp tile 32x16.
#define CROWS 64
#define CCOLS 64
#define PADK 136
#define OFF_A_HI 0
#define OFF_A_LO (CROWS * PADK * 2)             // 17408
#define OFF_B_HI (OFF_A_LO + CROWS * PADK * 2)  // 34816
#define OFF_B_LO (OFF_B_HI + CCOLS * PADK * 2)  // 52224
#define GEMM_SMEM (OFF_B_LO + CCOLS * PADK * 2) // 69632
#define BSTRIDE 68                               // bounce stride (floats)

__global__ __launch_bounds__(256, 3) void k_gemm_mma(const float* __restrict__ x,
                                                     const float* __restrict__ a_src,
                                                     const float* __restrict__ a_trg) {
    extern __shared__ char smem[];
    unsigned short* A_hi = (unsigned short*)(smem + OFF_A_HI);
    unsigned short* A_lo = (unsigned short*)(smem + OFF_A_LO);
    unsigned short* B_hi = (unsigned short*)(smem + OFF_B_HI);
    unsigned short* B_lo = (unsigned short*)(smem + OFF_B_LO);

    const int tid = threadIdx.x;
    const int wid = tid >> 5, lane = tid & 31;
    const int row0 = blockIdx.x * CROWS;
    const int col0 = blockIdx.y * CCOLS;

    // ---- load x tile (64 rows, full K), split to bf16 hi/lo ----
    for (int idx = tid; idx < CROWS * 16; idx += 256) {   // 4 iters
        int r = idx >> 4, c8 = idx & 15;
        int gr = row0 + r;
        float v[8];
        if (gr < N_NODES) {
            float4 p0 = *(const float4*)&x[(size_t)gr * FIN + c8 * 8];
            float4 p1 = *(const float4*)&x[(size_t)gr * FIN + c8 * 8 + 4];
            v[0]=p0.x; v[1]=p0.y; v[2]=p0.z; v[3]=p0.w;
            v[4]=p1.x; v[5]=p1.y; v[6]=p1.z; v[7]=p1.w;
        } else {
#pragma unroll
            for (int j = 0; j < 8; j++) v[j] = 0.f;
        }
        uint32_t hp[4], lp[4];
#pragma unroll
        for (int j = 0; j < 4; j++) {
            __nv_bfloat16 h0 = __float2bfloat16(v[2*j]);
            __nv_bfloat16 h1 = __float2bfloat16(v[2*j+1]);
            __nv_bfloat16 l0 = __float2bfloat16(v[2*j]   - __bfloat162float(h0));
            __nv_bfloat16 l1 = __float2bfloat16(v[2*j+1] - __bfloat162float(h1));
            hp[j] = (uint32_t)__bfloat16_as_ushort(h0) | ((uint32_t)__bfloat16_as_ushort(h1) << 16);
            lp[j] = (uint32_t)__bfloat16_as_ushort(l0) | ((uint32_t)__bfloat16_as_ushort(l1) << 16);
        }
        *(uint4*)&A_hi[r * PADK + c8 * 8] = make_uint4(hp[0], hp[1], hp[2], hp[3]);
        *(uint4*)&A_lo[r * PADK + c8 * 8] = make_uint4(lp[0], lp[1], lp[2], lp[3]);
    }
    // ---- copy this CTA's 64-col half of B images ----
    for (int idx = tid; idx < 1024; idx += 256) {
        int n = idx >> 4, q = idx & 15;
        *(uint4*)&B_hi[n * PADK + q * 8] = *(const uint4*)&g_Bhi[(col0 + n) * FIN + q * 8];
        *(uint4*)&B_lo[n * PADK + q * 8] = *(const uint4*)&g_Blo[(col0 + n) * FIN + q * 8];
    }
    __syncthreads();

    // ---- mainloop: ldmatrix fragments, 3 passes ----
    const int m0 = (wid & 1) * 32;
    const int n0 = (wid >> 1) * 16;
    const int lr = lane >> 2;
    const int lc = (lane & 3) * 2;

    const uint32_t sbu = smem_u32(smem);
    const int a_row = m0 + (lane & 15);
    const int a_c8  = (lane >> 4) * 8;
    const uint32_t aH0 = sbu + OFF_A_HI + (uint32_t)(a_row * PADK + a_c8) * 2;
    const uint32_t aL0 = sbu + OFF_A_LO + (uint32_t)(a_row * PADK + a_c8) * 2;
    const int b_row = n0 + ((lane >> 4) << 3) + (lane & 7);
    const int b_c8  = ((lane >> 3) & 1) * 8;
    const uint32_t bH0 = sbu + OFF_B_HI + (uint32_t)(b_row * PADK + b_c8) * 2;
    const uint32_t bL0 = sbu + OFF_B_LO + (uint32_t)(b_row * PADK + b_c8) * 2;
    const uint32_t STEP16 = 16 * PADK * 2;

    float c[2][2][4];
#pragma unroll
    for (int mi = 0; mi < 2; mi++)
#pragma unroll
        for (int ni = 0; ni < 2; ni++)
#pragma unroll
            for (int r = 0; r < 4; r++) c[mi][ni][r] = 0.f;

#pragma unroll
    for (int ks = 0; ks < 8; ks++) {
        const uint32_t koff = (uint32_t)(ks * 32);
        uint32_t ah[2][4], al[2][4], bh[2][2], bl[2][2];
        LDSM4(ah[0][0], ah[0][1], ah[0][2], ah[0][3], aH0 + koff);
        LDSM4(ah[1][0], ah[1][1], ah[1][2], ah[1][3], aH0 + STEP16 + koff);
        LDSM4(al[0][0], al[0][1], al[0][2], al[0][3], aL0 + koff);
        LDSM4(al[1][0], al[1][1], al[1][2], al[1][3], aL0 + STEP16 + koff);
        LDSM4(bh[0][0], bh[0][1], bh[1][0], bh[1][1], bH0 + koff);
        LDSM4(bl[0][0], bl[0][1], bl[1][0], bl[1][1], bL0 + koff);
#pragma unroll
        for (int mi = 0; mi < 2; mi++)
#pragma unroll
            for (int ni = 0; ni < 2; ni++) {
                mma16816(c[mi][ni], ah[mi], bh[ni]);
                mma16816(c[mi][ni], ah[mi], bl[ni]);
                mma16816(c[mi][ni], al[mi], bh[ni]);
            }
    }
    __syncthreads();

    // ---- bounce accumulators to smem ----
    float* bounce = (float*)smem;             // [64][68]
#pragma unroll
    for (int mi = 0; mi < 2; mi++) {
        int row = m0 + mi * 16 + lr;
#pragma unroll
        for (int ni = 0; ni < 2; ni++) {
            int col = n0 + ni * 8 + lc;
            bounce[row * BSTRIDE + col]           = c[mi][ni][0];
            bounce[row * BSTRIDE + col + 1]       = c[mi][ni][1];
            bounce[(row + 8) * BSTRIDE + col]     = c[mi][ni][2];
            bounce[(row + 8) * BSTRIDE + col + 1] = c[mi][ni][3];
        }
    }
    __syncthreads();

    // ---- per-row head dots ----
    if (tid < 128) {
        int r = tid >> 1, hl = tid & 1;
        int gr = row0 + r;
        if (gr < N_NODES) {
            int h = (col0 >> 5) + hl;
            const float* rowp = &bounce[r * BSTRIDE + hl * 32];
            float ps = 0.f, pt = 0.f;
#pragma unroll
            for (int j = 0; j < 32; j++) {
                float vv = rowp[j];
                ps = fmaf(vv, __ldg(&a_src[h * 32 + j]), ps);
                pt = fmaf(vv, __ldg(&a_trg[h * 32 + j]), pt);
            }
            g_s_src[gr * NH + h] = ps;
            g_s_trg[gr * NH + h] = pt;
        }
    }

    // ---- coalesced fp16 proj copy-out ----
    const int valid = min(CROWS, N_NODES - row0);
    for (int idx = tid; idx < valid * 32; idx += 256) {
        int r = idx >> 5, c2i = idx & 31;
        float2 f = make_float2(bounce[r * BSTRIDE + c2i * 2],
                               bounce[r * BSTRIDE + c2i * 2 + 1]);
        ((__half2*)&g_projh[(size_t)(row0 + r) * FIN + col0])[c2i] = __float22half2_rn(f);
    }
}

// ---------------- kernel: global max over leaky edge scores --------------
__global__ void k_edge_max(const int* __restrict__ ei, int E) {
    float m = __uint_as_float(0xFF800000u);
    int i = blockIdx.x * blockDim.x + threadIdx.x;
    int stride = gridDim.x * blockDim.x;
    for (; i < E; i += stride) {
        int src = ei[i];
        int trg = ei[E + i];
        float4 ss = *(const float4*)&g_s_src[src * NH];
        float4 st = *(const float4*)&g_s_trg[trg * NH];
        m = fmaxf(m, fmaxf(fmaxf(leaky(ss.x + st.x), leaky(ss.y + st.y)),
                           fmaxf(leaky(ss.z + st.z), leaky(ss.w + st.w))));
    }
#pragma unroll
    for (int o = 16; o >= 1; o >>= 1) m = fmaxf(m, __shfl_xor_sync(0xffffffffu, m, o));
    __shared__ float sm[8];
    int lane = threadIdx.x & 31, warp = threadIdx.x >> 5;
    if (lane == 0) sm[warp] = m;
    __syncthreads();
    if (warp == 0) {
        m = (lane < 8) ? sm[lane] : __uint_as_float(0xFF800000u);
#pragma unroll
        for (int o = 4; o >= 1; o >>= 1) m = fmaxf(m, __shfl_xor_sync(0xffffffffu, m, o));
        if (lane == 0) atomicMaxFloat(&g_max, m);
    }
}

// ---------------- kernel: aggregate (lane-parallel scores) + epilogue ----
// Phase 1 (parallel): lane k loads idx+scores+exp for edge k of its node.
// Phase 2 (loop): only proj gather + smem reads on the serial path.
__global__ __launch_bounds__(256) void k_node(const float* __restrict__ x,
                                              const float* __restrict__ bias,
                                              float* __restrict__ out) {
    __shared__ int   s_idx[8][32];
    __shared__ float s_e[8][32][4];   // [warp][edge][head] -> broadcast-friendly
    const int wline = threadIdx.x >> 5;
    int n = (blockIdx.x * blockDim.x + threadIdx.x) >> 5;
    if (n >= N_NODES) return;
    const int lane = threadIdx.x & 31;
    const int head = lane >> 3;
    const int start = g_off[n];
    const int deg = g_cnt[n];
    const float gm = g_max;
    float4 st4 = *(const float4*)&g_s_trg[n * NH];

    float4 acc = make_float4(0.f, 0.f, 0.f, 0.f);
    float d = 0.f;

    for (int base = 0; base < deg; base += 32) {
        const int cnt = min(32, deg - base);
        // phase 1: parallel score round
        int msrc = 0;
        float4 e4 = make_float4(0.f, 0.f, 0.f, 0.f);
        if (lane < cnt) {
            msrc = g_esrc[start + base + lane];
            float4 ss = *(const float4*)&g_s_src[msrc * NH];
            e4.x = expf(leaky(ss.x + st4.x) - gm);
            e4.y = expf(leaky(ss.y + st4.y) - gm);
            e4.z = expf(leaky(ss.z + st4.z) - gm);
            e4.w = expf(leaky(ss.w + st4.w) - gm);
        }
        s_idx[wline][lane] = msrc;
        *(float4*)&s_e[wline][lane][0] = e4;
        __syncwarp();

        // phase 2: proj gather loop (unroll 4 for MLP)
        int k = 0;
        for (; k + 3 < cnt; k += 4) {
            int i0 = s_idx[wline][k],     i1 = s_idx[wline][k + 1];
            int i2 = s_idx[wline][k + 2], i3 = s_idx[wline][k + 3];
            float e0 = s_e[wline][k][head],     e1 = s_e[wline][k + 1][head];
            float e2 = s_e[wline][k + 2][head], e3 = s_e[wline][k + 3][head];
            uint2 h0 = *(const uint2*)&g_projh[(size_t)i0 * FIN + lane * 4];
            uint2 h1 = *(const uint2*)&g_projh[(size_t)i1 * FIN + lane * 4];
            uint2 h2 = *(const uint2*)&g_projh[(size_t)i2 * FIN + lane * 4];
            uint2 h3 = *(const uint2*)&g_projh[(size_t)i3 * FIN + lane * 4];
            d += e0 + e1 + e2 + e3;
            float2 p00 = __half22float2(*(const __half2*)&h0.x);
            float2 p01 = __half22float2(*(const __half2*)&h0.y);
            float2 p10 = __half22float2(*(const __half2*)&h1.x);
            float2 p11 = __half22float2(*(const __half2*)&h1.y);
            float2 p20 = __half22float2(*(const __half2*)&h2.x);
            float2 p21 = __half22float2(*(const __half2*)&h2.y);
            float2 p30 = __half22float2(*(const __half2*)&h3.x);
            float2 p31 = __half22float2(*(const __half2*)&h3.y);
            acc.x = fmaf(p00.x, e0, acc.x); acc.x = fmaf(p10.x, e1, acc.x);
            acc.x = fmaf(p20.x, e2, acc.x); acc.x = fmaf(p30.x, e3, acc.x);
            acc.y = fmaf(p00.y, e0, acc.y); acc.y = fmaf(p10.y, e1, acc.y);
            acc.y = fmaf(p20.y, e2, acc.y); acc.y = fmaf(p30.y, e3, acc.y);
            acc.z = fmaf(p01.x, e0, acc.z); acc.z = fmaf(p11.x, e1, acc.z);
            acc.z = fmaf(p21.x, e2, acc.z); acc.z = fmaf(p31.x, e3, acc.z);
            acc.w = fmaf(p01.y, e0, acc.w); acc.w = fmaf(p11.y, e1, acc.w);
            acc.w = fmaf(p21.y, e2, acc.w); acc.w = fmaf(p31.y, e3, acc.w);
        }
        for (; k < cnt; k++) {
            int i0 = s_idx[wline][k];
            float e0 = s_e[wline][k][head];
            uint2 h0 = *(const uint2*)&g_projh[(size_t)i0 * FIN + lane * 4];
            d += e0;
            float2 p00 = __half22float2(*(const __half2*)&h0.x);
            float2 p01 = __half22float2(*(const __half2*)&h0.y);
            acc.x = fmaf(p00.x, e0, acc.x);
            acc.y = fmaf(p00.y, e0, acc.y);
            acc.z = fmaf(p01.x, e0, acc.z);
            acc.w = fmaf(p01.y, e0, acc.w);
        }
        __syncwarp();
    }

    const float rd = 1.f / (d + 1e-16f);
    float4 xb = *(const float4*)&x[n * FIN + lane * 4];
    float4 bb = *(const float4*)&bias[lane * 4];
    float4 r;
    r.x = fmaf(acc.x, rd, xb.x + bb.x); r.x = r.x > 0.f ? r.x : expm1f(r.x);
    r.y = fmaf(acc.y, rd, xb.y + bb.y); r.y = r.y > 0.f ? r.y : expm1f(r.y);
    r.z = fmaf(acc.z, rd, xb.z + bb.z); r.z = r.z > 0.f ? r.z : expm1f(r.z);
    r.w = fmaf(acc.w, rd, xb.w + bb.w); r.w = r.w > 0.f ? r.w : expm1f(r.w);
    *(float4*)&out[n * FIN + lane * 4] = r;
}

// ---------------- launch: graph-forked CSR build || GEMM -----------------
extern "C" void kernel_launch(void* const* d_in, const int* in_sizes, int n_in,
                              void* d_out, int out_size) {
    const float* x     = (const float*)d_in[0];
    const int*   ei    = (const int*)d_in[1];   // JAX x64 disabled: int32
    const float* W     = (const float*)d_in[2];
    const float* a_src = (const float*)d_in[3];
    const float* a_trg = (const float*)d_in[4];
    const float* bias  = (const float*)d_in[5];
    float* out = (float*)d_out;

    const int E = in_sizes[1] / 2;

    static cudaStream_t s2 = nullptr;
    static cudaEvent_t evFork = nullptr, evJoin = nullptr;
    if (s2 == nullptr) {
        cudaStreamCreateWithFlags(&s2, cudaStreamNonBlocking);
        cudaEventCreateWithFlags(&evFork, cudaEventDisableTiming);
        cudaEventCreateWithFlags(&evJoin, cudaEventDisableTiming);
        cudaFuncSetAttribute(k_gemm_mma, cudaFuncAttributeMaxDynamicSharedMemorySize, GEMM_SMEM);
    }

    k_init<<<NB_CHUNKS, 256>>>(W);

    // fork: full CSR build (count/offsets/scatter) on s2, GEMM on main
    cudaEventRecord(evFork, 0);
    cudaStreamWaitEvent(s2, evFork, 0);
    k_count<<<(E + 255) / 256, 256, 0, s2>>>(ei, E);
    k_offsets<<<NB_CHUNKS, 256, 0, s2>>>();
    k_scatter<<<(E + 255) / 256, 256, 0, s2>>>(ei, E);
    cudaEventRecord(evJoin, s2);

    dim3 ggrid((N_NODES + CROWS - 1) / CROWS, FIN / CCOLS);
    k_gemm_mma<<<ggrid, 256, GEMM_SMEM>>>(x, a_src, a_trg);

    // max needs scores (GEMM); node needs max + CSR
    k_edge_max<<<1024, 256>>>(ei, E);
    cudaStreamWaitEvent(0, evJoin, 0);
    k_node<<<(N_NODES * 32 + 255) / 256, 256>>>(x, bias, out);
}